// round 2
// baseline (speedup 1.0000x reference)
#include <cuda_runtime.h>

#define N_  2
#define T_  2048
#define D_  512
#define H_  8
#define HD_ 64
#define NTD (N_*T_*D_)          // 2097152 elements per stream output
#define NHTHD (N_*H_*T_*HD_)    // 2097152
#define PAD 68

// Scratch: [stream][q/k/v][n,h,t,hd]
__device__ float g_buf[2][3][NHTHD];
// softmaxed per-head scale: [stream][h*64+hd]
__device__ float g_sc[2][H_*HD_];
// raw score scratch: per block 16 tiles x 2048 float4 (f4 = 4 q-rows of one col)
// layout: [blk][kt][j(8)][tid(256)] as float4 -> fully coalesced
__device__ float4 g_S[1024 * 16 * 2048];

// ---------------------------------------------------------------------------
// Kernel 1: softmax of the (H,1,HD) scale params over HD (tiny)
// ---------------------------------------------------------------------------
__global__ void scale_kernel(const float* __restrict__ isc,
                             const float* __restrict__ lsc) {
    int i = threadIdx.x;
    if (i >= 16) return;
    int s = i >> 3, h = i & 7;
    const float* src = (s == 0 ? isc : lsc) + h * HD_;
    float m = -1e30f;
    for (int d = 0; d < HD_; d++) m = fmaxf(m, src[d]);
    float Z = 0.f;
    for (int d = 0; d < HD_; d++) Z += __expf(src[d] - m);
    float inv = 1.f / Z;
    for (int d = 0; d < HD_; d++) g_sc[s][h*HD_ + d] = __expf(src[d] - m) * inv;
}

// ---------------------------------------------------------------------------
// helpers
// ---------------------------------------------------------------------------
__device__ __forceinline__ void fma44(float (&acc)[4][4], float4 a, float4 b) {
    acc[0][0] += a.x*b.x; acc[0][1] += a.x*b.y; acc[0][2] += a.x*b.z; acc[0][3] += a.x*b.w;
    acc[1][0] += a.y*b.x; acc[1][1] += a.y*b.y; acc[1][2] += a.y*b.z; acc[1][3] += a.y*b.w;
    acc[2][0] += a.z*b.x; acc[2][1] += a.z*b.y; acc[2][2] += a.z*b.z; acc[2][3] += a.z*b.w;
    acc[3][0] += a.w*b.x; acc[3][1] += a.w*b.y; acc[3][2] += a.w*b.z; acc[3][3] += a.w*b.w;
}

__device__ __forceinline__ void fma48(float (&acc)[4][8], float4 a, float4 b0, float4 b1) {
    acc[0][0] += a.x*b0.x; acc[0][1] += a.x*b0.y; acc[0][2] += a.x*b0.z; acc[0][3] += a.x*b0.w;
    acc[0][4] += a.x*b1.x; acc[0][5] += a.x*b1.y; acc[0][6] += a.x*b1.z; acc[0][7] += a.x*b1.w;
    acc[1][0] += a.y*b0.x; acc[1][1] += a.y*b0.y; acc[1][2] += a.y*b0.z; acc[1][3] += a.y*b0.w;
    acc[1][4] += a.y*b1.x; acc[1][5] += a.y*b1.y; acc[1][6] += a.y*b1.z; acc[1][7] += a.y*b1.w;
    acc[2][0] += a.z*b0.x; acc[2][1] += a.z*b0.y; acc[2][2] += a.z*b0.z; acc[2][3] += a.z*b0.w;
    acc[2][4] += a.z*b1.x; acc[2][5] += a.z*b1.y; acc[2][6] += a.z*b1.z; acc[2][7] += a.z*b1.w;
    acc[3][0] += a.w*b0.x; acc[3][1] += a.w*b0.y; acc[3][2] += a.w*b0.z; acc[3][3] += a.w*b0.w;
    acc[3][4] += a.w*b1.x; acc[3][5] += a.w*b1.y; acc[3][6] += a.w*b1.z; acc[3][7] += a.w*b1.w;
}

__device__ __forceinline__ float red_max16(float v) {
    v = fmaxf(v, __shfl_xor_sync(0xffffffffu, v, 1));
    v = fmaxf(v, __shfl_xor_sync(0xffffffffu, v, 2));
    v = fmaxf(v, __shfl_xor_sync(0xffffffffu, v, 4));
    v = fmaxf(v, __shfl_xor_sync(0xffffffffu, v, 8));
    return v;
}
__device__ __forceinline__ float red_sum16(float v) {
    v += __shfl_xor_sync(0xffffffffu, v, 1);
    v += __shfl_xor_sync(0xffffffffu, v, 2);
    v += __shfl_xor_sync(0xffffffffu, v, 4);
    v += __shfl_xor_sync(0xffffffffu, v, 8);
    return v;
}

// ---------------------------------------------------------------------------
// Kernel 2: QKV GEMM  out[m,c] = sum_k z[m,k]*W[c,k], scatter to g_buf
// (unchanged from R1 — not the bottleneck)
// ---------------------------------------------------------------------------
__global__ __launch_bounds__(256)
void qkv_kernel(const float* __restrict__ z, const float* __restrict__ W, int stream) {
    __shared__ float as[32][PAD];   // [k][m]
    __shared__ float bs[32][PAD];   // [k][c]
    int tid = threadIdx.x;
    int ty = tid >> 4, tx = tid & 15;
    int c0 = blockIdx.x * 64;
    int m0 = blockIdx.y * 64;

    float acc[4][4] = {};
    for (int k0 = 0; k0 < 512; k0 += 32) {
        __syncthreads();
        #pragma unroll
        for (int p = 0; p < 8; p++) {
            int idx = tid + p * 256;
            int mm = idx >> 5, kk = idx & 31;
            as[kk][mm] = z[(m0 + mm) * 512 + k0 + kk];
            bs[kk][mm] = W[(c0 + mm) * 512 + k0 + kk];
        }
        __syncthreads();
        #pragma unroll
        for (int k = 0; k < 32; k++) {
            float4 av = *(const float4*)&as[k][ty * 4];
            float4 bv = *(const float4*)&bs[k][tx * 4];
            fma44(acc, av, bv);
        }
    }

    int three = c0 >> 9;
    int h = (c0 >> 6) & 7;
    float* dst = g_buf[stream][three];
    bool isq = (three == 0);
    int hd = tx * 4;
    float4 s4 = make_float4(1.f, 1.f, 1.f, 1.f);
    if (isq) s4 = *(const float4*)&g_sc[stream][h * HD_ + hd];

    #pragma unroll
    for (int i = 0; i < 4; i++) {
        int mm = m0 + ty * 4 + i;
        int nn = mm >> 11, t = mm & 2047;
        float4 v = make_float4(acc[i][0] * s4.x, acc[i][1] * s4.y,
                               acc[i][2] * s4.z, acc[i][3] * s4.w);
        *(float4*)&dst[((nn * H_ + h) * T_ + t) * HD_ + hd] = v;
    }
}

// ---------------------------------------------------------------------------
// Kernel 3: fused dual attention, two passes via S scratch.
// Block = one (stream, n, h, 64-row q-tile). 256 threads.
// Pass 1: 128-key tiles, 4x8 micro QK^T, raw S -> gmem, online (m,Z).
// Pass 2: S re-read (own values), a=exp(S-m)/Z, w=exp(-a) into swizzled smem,
//         concat-GEMM: tx<8 -> attn*Vc, tx>=8 -> anti*Vf (4x8 micro each).
// anti = softmax(max(attn)-attn) == softmax(-attn) -> w = exp(-attn)/sum(w)
// ---------------------------------------------------------------------------
__global__ __launch_bounds__(256)
void attn_kernel(const float* __restrict__ sp, float* __restrict__ out) {
    extern __shared__ float sm[];
    // pass-2 layout (pass-1 qs/ks overlay the low region)
    float* vc = sm;              // [128][64]   8192 floats
    float* vf = sm + 8192;       // [128][64]   8192 floats
    float* at = sm + 16384;      // swizzled, 128*17 float4 = 8704 floats
    float* wt = sm + 25088;      // swizzled, 8704 floats
    float* qs = sm;              // pass1: [64][68]  4352 floats
    float* ks = sm + 4352;       // pass1: [64][132] 8448 floats

    int tid = threadIdx.x;
    int ty = tid >> 4, tx = tid & 15;
    int qt = blockIdx.x;
    int h  = blockIdx.y;
    int zb = blockIdx.z;
    int s  = zb >> 1, n = zb & 1;
    int blk = (zb * 8 + h) * 32 + qt;

    const float* Qb  = g_buf[s][0]     + ((n * H_ + h) * T_ + qt * 64) * HD_;
    const float* Kb  = g_buf[1 - s][1] + ((n * H_ + h) * T_) * HD_;
    const float* Vcb = g_buf[1 - s][2] + ((n * H_ + h) * T_) * HD_;
    const float* Vsb = g_buf[s][2]     + ((n * H_ + h) * T_) * HD_;
    float* ob = out + s * NTD;
    float spv = *sp;

    // load Q tile transposed [d][r]
    for (int idx = tid; idx < 4096; idx += 256) {
        int r = idx >> 6, d = idx & 63;
        qs[d * 68 + r] = Qb[r * 64 + d];
    }

    float m[4], Zs[4];
    #pragma unroll
    for (int i = 0; i < 4; i++) { m[i] = -1e30f; Zs[i] = 0.f; }

    // ---- pass 1: QK^T (128-key tiles), S -> gmem, online stats ----
    for (int kt = 0; kt < 16; kt++) {
        __syncthreads();
        for (int idx = tid; idx < 8192; idx += 256) {
            int c = idx >> 6, d = idx & 63;
            ks[d * 132 + c] = Kb[(kt * 128 + c) * 64 + d];
        }
        __syncthreads();
        float S[4][8] = {};
        #pragma unroll
        for (int d = 0; d < 64; d++) {
            float4 qv = ((const float4*)qs)[d * 17 + ty];
            float4 k0 = ((const float4*)ks)[d * 33 + tx * 2];
            float4 k1 = ((const float4*)ks)[d * 33 + tx * 2 + 1];
            fma48(S, qv, k0, k1);
        }
        // store raw S: f4 = (rows ty*4..+3) of col tx*8+j, coalesced over tid
        float4* Sg = g_S + (((blk << 4) + kt) << 11) + tid;
        #pragma unroll
        for (int j = 0; j < 8; j++)
            Sg[j << 8] = make_float4(S[0][j], S[1][j], S[2][j], S[3][j]);
        #pragma unroll
        for (int i = 0; i < 4; i++) {
            float tm = S[i][0];
            #pragma unroll
            for (int j = 1; j < 8; j++) tm = fmaxf(tm, S[i][j]);
            tm = red_max16(tm);
            float mn = fmaxf(m[i], tm);
            float ls = 0.f;
            #pragma unroll
            for (int j = 0; j < 8; j++) ls += __expf(S[i][j] - mn);
            ls = red_sum16(ls);
            Zs[i] = Zs[i] * __expf(m[i] - mn) + ls;
            m[i] = mn;
        }
    }

    float invZ[4], sw[4];
    #pragma unroll
    for (int i = 0; i < 4; i++) { invZ[i] = 1.f / Zs[i]; sw[i] = 0.f; }

    float acc[4][8] = {};
    bool self = (tx >= 8);
    int dcol = (tx & 7) * 8;

    // ---- pass 2: a/w generation + concat AV GEMM ----
    for (int kt = 0; kt < 16; kt++) {
        __syncthreads();
        for (int idx = tid; idx < 8192; idx += 256) {
            int c = idx >> 6, d = idx & 63;
            int g = (kt * 128 + c) * 64 + d;
            vc[c * 64 + d] = Vcb[g];
            vf[c * 64 + d] = Vsb[g];
        }
        const float4* Sg = g_S + (((blk << 4) + kt) << 11) + tid;
        #pragma unroll
        for (int j = 0; j < 8; j++) {
            float4 s4 = Sg[j << 8];
            float4 av, wv;
            av.x = __expf(s4.x - m[0]) * invZ[0];
            av.y = __expf(s4.y - m[1]) * invZ[1];
            av.z = __expf(s4.z - m[2]) * invZ[2];
            av.w = __expf(s4.w - m[3]) * invZ[3];
            wv.x = __expf(-av.x);
            wv.y = __expf(-av.y);
            wv.z = __expf(-av.z);
            wv.w = __expf(-av.w);
            sw[0] += wv.x; sw[1] += wv.y; sw[2] += wv.z; sw[3] += wv.w;
            int c = tx * 8 + j;
            int slot = c * 17 + (ty ^ ((c >> 3) & 7));
            ((float4*)at)[slot] = av;
            ((float4*)wt)[slot] = wv;
        }
        __syncthreads();
        const float* Ab = self ? wt : at;
        const float* Vb = self ? vf : vc;
        #pragma unroll 8
        for (int c = 0; c < 128; c++) {
            int slot = c * 17 + (ty ^ ((c >> 3) & 7));
            float4 a4 = ((const float4*)Ab)[slot];
            float4 v0 = *(const float4*)&Vb[c * 64 + dcol];
            float4 v1 = *(const float4*)&Vb[c * 64 + dcol + 4];
            fma48(acc, a4, v0, v1);
        }
    }

    // reduce anti-weight row sums across the 16 tx lanes (each summed its 8 cols/tile)
    #pragma unroll
    for (int i = 0; i < 4; i++) sw[i] = red_sum16(sw[i]);

    // combine: self half stages (1-s)*os/sw, cross half adds s*oc and writes out
    __syncthreads();
    float oms = 1.0f - spv;
    float* stage = vc;   // reuse, [64][64]
    if (self) {
        #pragma unroll
        for (int i = 0; i < 4; i++) {
            float iw = oms / sw[i];
            int r = ty * 4 + i;
            *(float4*)&stage[r * 64 + dcol] =
                make_float4(acc[i][0]*iw, acc[i][1]*iw, acc[i][2]*iw, acc[i][3]*iw);
            *(float4*)&stage[r * 64 + dcol + 4] =
                make_float4(acc[i][4]*iw, acc[i][5]*iw, acc[i][6]*iw, acc[i][7]*iw);
        }
    }
    __syncthreads();
    if (!self) {
        #pragma unroll
        for (int i = 0; i < 4; i++) {
            int r = ty * 4 + i;
            int t = qt * 64 + r;
            float4 s0 = *(const float4*)&stage[r * 64 + dcol];
            float4 s1 = *(const float4*)&stage[r * 64 + dcol + 4];
            float4 o0 = make_float4(spv*acc[i][0]+s0.x, spv*acc[i][1]+s0.y,
                                    spv*acc[i][2]+s0.z, spv*acc[i][3]+s0.w);
            float4 o1 = make_float4(spv*acc[i][4]+s1.x, spv*acc[i][5]+s1.y,
                                    spv*acc[i][6]+s1.z, spv*acc[i][7]+s1.w);
            float* op = &ob[(n * T_ + t) * D_ + h * HD_ + dcol];
            *(float4*)op = o0;
            *(float4*)(op + 4) = o1;
        }
    }
}

// ---------------------------------------------------------------------------
extern "C" void kernel_launch(void* const* d_in, const int* in_sizes, int n_in,
                              void* d_out, int out_size) {
    const float* x   = (const float*)d_in[0];
    const float* y   = (const float*)d_in[1];
    const float* iw  = (const float*)d_in[2];
    const float* lw  = (const float*)d_in[3];
    const float* isc = (const float*)d_in[4];
    const float* lsc = (const float*)d_in[5];
    const float* sp  = (const float*)d_in[6];
    float* out = (float*)d_out;

    const int ATTN_SMEM = 33792 * 4;   // 135168 bytes
    cudaFuncSetAttribute(attn_kernel, cudaFuncAttributeMaxDynamicSharedMemorySize, ATTN_SMEM);

    scale_kernel<<<1, 32>>>(isc, lsc);

    dim3 g1(1536 / 64, 4096 / 64);
    qkv_kernel<<<g1, 256>>>(x, iw, 0);
    qkv_kernel<<<g1, 256>>>(y, lw, 1);

    dim3 g2(T_ / 64, H_, 4);
    attn_kernel<<<g2, 256, ATTN_SMEM>>>(sp, out);
}

// round 4
// speedup vs baseline: 3.1891x; 3.1891x over previous
#include <cuda_runtime.h>
#include <cstdint>

#define N_  2
#define T_  2048
#define D_  512
#define H_  8
#define HD_ 64
#define NTD (N_*T_*D_)
#define NHTHD (N_*H_*T_*HD_)
#define PAD 68

// Scratch: [stream][q/k/v][n,h,t,hd]
__device__ float g_buf[2][3][NHTHD];
__device__ float g_sc[2][H_*HD_];
// p scratch: [blk(512)][warp(8)][kt(32)][j(8)*lane(32)] float4 (A-frag layout)
__device__ float4 g_p[512u*8u*32u*256u];

// smem word offsets (32-bit words)
#define QP 0        // qpack: 64 frag-groups * 132
#define KP 8448     // kpack: 64 frag-groups * 66
#define MR 12672    // running-max table: 8 warps * 512
#define VC 0        // pass2: vcpack 64 * 66
#define VF 4224     // pass2: vfpack 64 * 66
#define CR 8448     // pass2: corr table 8 * 512
#define SMEM_WORDS 16768

// ---------------------------------------------------------------------------
__global__ void scale_kernel(const float* __restrict__ isc,
                             const float* __restrict__ lsc) {
    int i = threadIdx.x;
    if (i >= 16) return;
    int s = i >> 3, h = i & 7;
    const float* src = (s == 0 ? isc : lsc) + h * HD_;
    float m = -1e30f;
    for (int d = 0; d < HD_; d++) m = fmaxf(m, src[d]);
    float Z = 0.f;
    for (int d = 0; d < HD_; d++) Z += __expf(src[d] - m);
    float inv = 1.f / Z;
    for (int d = 0; d < HD_; d++) g_sc[s][h*HD_ + d] = __expf(src[d] - m) * inv;
}

__device__ __forceinline__ void fma44(float (&acc)[4][4], float4 a, float4 b) {
    acc[0][0] += a.x*b.x; acc[0][1] += a.x*b.y; acc[0][2] += a.x*b.z; acc[0][3] += a.x*b.w;
    acc[1][0] += a.y*b.x; acc[1][1] += a.y*b.y; acc[1][2] += a.y*b.z; acc[1][3] += a.y*b.w;
    acc[2][0] += a.z*b.x; acc[2][1] += a.z*b.y; acc[2][2] += a.z*b.z; acc[2][3] += a.z*b.w;
    acc[3][0] += a.w*b.x; acc[3][1] += a.w*b.y; acc[3][2] += a.w*b.z; acc[3][3] += a.w*b.w;
}

__device__ __forceinline__ uint32_t f2tf(float x) {
    uint32_t r;
    asm("cvt.rna.tf32.f32 %0, %1;" : "=r"(r) : "f"(x));
    return r;
}

__device__ __forceinline__ void mma_tf32(float (&d)[4],
                                         uint32_t a0, uint32_t a1, uint32_t a2, uint32_t a3,
                                         uint32_t b0, uint32_t b1) {
    asm volatile(
        "mma.sync.aligned.m16n8k8.row.col.f32.tf32.tf32.f32 "
        "{%0,%1,%2,%3}, {%4,%5,%6,%7}, {%8,%9}, {%0,%1,%2,%3};"
        : "+f"(d[0]), "+f"(d[1]), "+f"(d[2]), "+f"(d[3])
        : "r"(a0), "r"(a1), "r"(a2), "r"(a3), "r"(b0), "r"(b1));
}

// ---------------------------------------------------------------------------
// Kernel 2: QKV GEMM (fp32, unchanged — protects V precision)
// ---------------------------------------------------------------------------
__global__ __launch_bounds__(256)
void qkv_kernel(const float* __restrict__ z, const float* __restrict__ W, int stream) {
    __shared__ float as[32][PAD];
    __shared__ float bs[32][PAD];
    int tid = threadIdx.x;
    int ty = tid >> 4, tx = tid & 15;
    int c0 = blockIdx.x * 64;
    int m0 = blockIdx.y * 64;

    float acc[4][4] = {};
    for (int k0 = 0; k0 < 512; k0 += 32) {
        __syncthreads();
        #pragma unroll
        for (int p = 0; p < 8; p++) {
            int idx = tid + p * 256;
            int mm = idx >> 5, kk = idx & 31;
            as[kk][mm] = z[(m0 + mm) * 512 + k0 + kk];
            bs[kk][mm] = W[(c0 + mm) * 512 + k0 + kk];
        }
        __syncthreads();
        #pragma unroll
        for (int k = 0; k < 32; k++) {
            float4 av = *(const float4*)&as[k][ty * 4];
            float4 bv = *(const float4*)&bs[k][tx * 4];
            fma44(acc, av, bv);
        }
    }

    int three = c0 >> 9;
    int h = (c0 >> 6) & 7;
    float* dst = g_buf[stream][three];
    bool isq = (three == 0);
    int hd = tx * 4;
    float4 s4 = make_float4(1.f, 1.f, 1.f, 1.f);
    if (isq) s4 = *(const float4*)&g_sc[stream][h * HD_ + hd];

    #pragma unroll
    for (int i = 0; i < 4; i++) {
        int mm = m0 + ty * 4 + i;
        int nn = mm >> 11, t = mm & 2047;
        float4 v = make_float4(acc[i][0] * s4.x, acc[i][1] * s4.y,
                               acc[i][2] * s4.z, acc[i][3] * s4.w);
        *(float4*)&dst[((nn * H_ + h) * T_ + t) * HD_ + hd] = v;
    }
}

// ---------------------------------------------------------------------------
// Kernel 3: dual attention, tf32 mma.sync, two-pass via p-scratch.
// Block = (stream s, batch n, head h, 128-row q-tile). 8 warps, 16 rows/warp.
// Pass 1: QK^T (64-key tiles), online (m,Z), p=exp(S-m_run) -> gmem A-frags.
// Pass 2: attn = p*corr, anti_w = exp(-attn); two tf32 AV mmas.
// anti = softmax(max(attn)-attn) == softmax(-attn)
// ---------------------------------------------------------------------------
__global__ __launch_bounds__(256)
void attn_kernel(const float* __restrict__ sp, float* __restrict__ out) {
    extern __shared__ uint32_t smu[];
    float* smf = (float*)smu;
    int tid = threadIdx.x;
    int w = tid >> 5, lane = tid & 31;
    int g = lane >> 2, c = lane & 3;
    int qt = blockIdx.x, h = blockIdx.y, zb = blockIdx.z;
    int s = zb >> 1, n = zb & 1;
    int blk = (zb * 8 + h) * 16 + qt;

    const float* Qb  = g_buf[s][0]     + ((n * H_ + h) * T_ + qt * 128) * HD_;
    const float* Kb  = g_buf[1 - s][1] + ((n * H_ + h) * T_) * HD_;
    const float* Vcb = g_buf[1 - s][2] + ((n * H_ + h) * T_) * HD_;
    const float* Vsb = g_buf[s][2]     + ((n * H_ + h) * T_) * HD_;
    float* ob = out + s * NTD;
    float spv = *sp;

    // pack Q tile [128x64] into tf32 A-fragment layout
    #pragma unroll
    for (int p = 0; p < 8; p++) {
        int i4 = tid + p * 256;
        int row = i4 >> 4, kq = i4 & 15;
        float4 qv = *(const float4*)&Qb[row * 64 + kq * 4];
        int base = QP + ((row >> 4) * 8 + (kq >> 1)) * 132 + (row & 7) * 16
                 + (kq & 1) * 2 + ((row >> 3) & 1);
        smu[base + 0]  = f2tf(qv.x);
        smu[base + 4]  = f2tf(qv.y);
        smu[base + 8]  = f2tf(qv.z);
        smu[base + 12] = f2tf(qv.w);
    }

    float m0 = -1e30f, m1 = -1e30f, Z0 = 0.f, Z1 = 0.f;

    // ======================= pass 1: QK^T + stats + p =======================
    for (int kt = 0; kt < 32; kt++) {
        __syncthreads();
        #pragma unroll
        for (int p = 0; p < 4; p++) {
            int i4 = tid + p * 256;
            int nn = i4 >> 4, kq = i4 & 15;
            float4 kv = *(const float4*)&Kb[(kt * 64 + nn) * 64 + kq * 4];
            int base = KP + ((nn >> 3) * 8 + (kq >> 1)) * 66 + (nn & 7) * 8 + (kq & 1);
            smu[base + 0] = f2tf(kv.x);
            smu[base + 2] = f2tf(kv.y);
            smu[base + 4] = f2tf(kv.z);
            smu[base + 6] = f2tf(kv.w);
        }
        __syncthreads();

        float S[8][4];
        #pragma unroll
        for (int j = 0; j < 8; j++) { S[j][0]=0.f; S[j][1]=0.f; S[j][2]=0.f; S[j][3]=0.f; }
        #pragma unroll
        for (int ks = 0; ks < 8; ks++) {
            uint4 a = *(const uint4*)&smu[QP + (w * 8 + ks) * 132 + lane * 4];
            #pragma unroll
            for (int j = 0; j < 8; j++) {
                uint2 b = *(const uint2*)&smu[KP + (j * 8 + ks) * 66 + lane * 2];
                mma_tf32(S[j], a.x, a.y, a.z, a.w, b.x, b.y);
            }
        }
        // online stats: rows g (S[j][0..1]) and g+8 (S[j][2..3]), quad-private
        float t0 = -1e30f, t1 = -1e30f;
        #pragma unroll
        for (int j = 0; j < 8; j++) {
            t0 = fmaxf(t0, fmaxf(S[j][0], S[j][1]));
            t1 = fmaxf(t1, fmaxf(S[j][2], S[j][3]));
        }
        t0 = fmaxf(t0, __shfl_xor_sync(~0u, t0, 1));
        t0 = fmaxf(t0, __shfl_xor_sync(~0u, t0, 2));
        t1 = fmaxf(t1, __shfl_xor_sync(~0u, t1, 1));
        t1 = fmaxf(t1, __shfl_xor_sync(~0u, t1, 2));
        float mn0 = fmaxf(m0, t0), mn1 = fmaxf(m1, t1);

        float P[8][4];
        float ps0 = 0.f, ps1 = 0.f;
        #pragma unroll
        for (int j = 0; j < 8; j++) {
            P[j][0] = __expf(S[j][0] - mn0);
            P[j][1] = __expf(S[j][1] - mn0);
            P[j][2] = __expf(S[j][2] - mn1);
            P[j][3] = __expf(S[j][3] - mn1);
            ps0 += P[j][0] + P[j][1];
            ps1 += P[j][2] + P[j][3];
        }
        ps0 += __shfl_xor_sync(~0u, ps0, 1);
        ps0 += __shfl_xor_sync(~0u, ps0, 2);
        ps1 += __shfl_xor_sync(~0u, ps1, 1);
        ps1 += __shfl_xor_sync(~0u, ps1, 2);
        Z0 = Z0 * __expf(m0 - mn0) + ps0; m0 = mn0;
        Z1 = Z1 * __expf(m1 - mn1) + ps1; m1 = mn1;
        if (c == 0) {
            smf[MR + w * 512 + kt * 16 + g]     = mn0;
            smf[MR + w * 512 + kt * 16 + g + 8] = mn1;
        }
        // shuffle C-frag -> A-frag layout; coalesced store of p
        int src1 = (lane & ~3) | (c >> 1);
        int src2 = src1 + 2;
        bool odd = (lane & 1);
        float4* pg = &g_p[((blk * 8 + w) * 32 + kt) * 256 + lane];
        #pragma unroll
        for (int j = 0; j < 8; j++) {
            float x0 = __shfl_sync(~0u, P[j][0], src1);
            float x1 = __shfl_sync(~0u, P[j][1], src1);
            float y0 = __shfl_sync(~0u, P[j][2], src1);
            float y1 = __shfl_sync(~0u, P[j][3], src1);
            float u0 = __shfl_sync(~0u, P[j][0], src2);
            float u1 = __shfl_sync(~0u, P[j][1], src2);
            float v0 = __shfl_sync(~0u, P[j][2], src2);
            float v1 = __shfl_sync(~0u, P[j][3], src2);
            float4 o;
            o.x = odd ? x1 : x0;   // a0: row g,   col c
            o.y = odd ? y1 : y0;   // a1: row g+8, col c
            o.z = odd ? u1 : u0;   // a2: row g,   col c+4
            o.w = odd ? v1 : v0;   // a3: row g+8, col c+4
            pg[j * 32] = o;
        }
    }

    // =================== corr table: exp(m_run - m_fin)/Z ===================
    float iZ0 = 1.f / Z0, iZ1 = 1.f / Z1;
    __syncthreads();
    #pragma unroll
    for (int i = 0; i < 16; i++) {
        int idx = lane + i * 32;
        int r = idx & 15;
        int srcl = (r & 7) * 4;
        float mfa = __shfl_sync(~0u, m0, srcl);
        float mfb = __shfl_sync(~0u, m1, srcl);
        float iza = __shfl_sync(~0u, iZ0, srcl);
        float izb = __shfl_sync(~0u, iZ1, srcl);
        float mf = (r < 8) ? mfa : mfb;
        float iz = (r < 8) ? iza : izb;
        float mr = smf[MR + w * 512 + idx];
        smf[CR + w * 512 + idx] = __expf(mr - mf) * iz;
    }

    // ======================= pass 2: attn/anti AV ===========================
    float accA[8][4], accW[8][4];
    #pragma unroll
    for (int dp = 0; dp < 8; dp++)
        #pragma unroll
        for (int e = 0; e < 4; e++) { accA[dp][e] = 0.f; accW[dp][e] = 0.f; }
    float sw0 = 0.f, sw1 = 0.f;

    for (int kt = 0; kt < 32; kt++) {
        __syncthreads();
        #pragma unroll
        for (int p = 0; p < 4; p++) {
            int i4 = tid + p * 256;
            int key = i4 >> 4, dq = i4 & 15;
            float4 va = *(const float4*)&Vcb[(kt * 64 + key) * 64 + dq * 4];
            float4 vb = *(const float4*)&Vsb[(kt * 64 + key) * 64 + dq * 4];
            int base = ((dq >> 1) * 8 + (key >> 3)) * 66 + (dq & 1) * 32
                     + (key & 3) * 2 + ((key >> 2) & 1);
            smu[VC + base + 0]  = f2tf(va.x);
            smu[VC + base + 8]  = f2tf(va.y);
            smu[VC + base + 16] = f2tf(va.z);
            smu[VC + base + 24] = f2tf(va.w);
            smu[VF + base + 0]  = f2tf(vb.x);
            smu[VF + base + 8]  = f2tf(vb.y);
            smu[VF + base + 16] = f2tf(vb.z);
            smu[VF + base + 24] = f2tf(vb.w);
        }
        __syncthreads();
        float cr0 = smf[CR + w * 512 + kt * 16 + g];
        float cr1 = smf[CR + w * 512 + kt * 16 + g + 8];
        const float4* pg = &g_p[((blk * 8 + w) * 32 + kt) * 256 + lane];
        #pragma unroll
        for (int j = 0; j < 8; j++) {
            float4 p4 = pg[j * 32];
            float a0 = p4.x * cr0, a1 = p4.y * cr1, a2 = p4.z * cr0, a3 = p4.w * cr1;
            float w0 = __expf(-a0), w1 = __expf(-a1), w2 = __expf(-a2), w3 = __expf(-a3);
            sw0 += w0 + w2; sw1 += w1 + w3;
            uint32_t aA0 = f2tf(a0), aA1 = f2tf(a1), aA2 = f2tf(a2), aA3 = f2tf(a3);
            uint32_t aW0 = f2tf(w0), aW1 = f2tf(w1), aW2 = f2tf(w2), aW3 = f2tf(w3);
            #pragma unroll
            for (int dp = 0; dp < 8; dp++) {
                uint2 bc = *(const uint2*)&smu[VC + (dp * 8 + j) * 66 + lane * 2];
                uint2 bf = *(const uint2*)&smu[VF + (dp * 8 + j) * 66 + lane * 2];
                mma_tf32(accA[dp], aA0, aA1, aA2, aA3, bc.x, bc.y);
                mma_tf32(accW[dp], aW0, aW1, aW2, aW3, bf.x, bf.y);
            }
        }
    }

    // anti row sums over full 2048 cols (reduce over quad lanes)
    sw0 += __shfl_xor_sync(~0u, sw0, 1);
    sw0 += __shfl_xor_sync(~0u, sw0, 2);
    sw1 += __shfl_xor_sync(~0u, sw1, 1);
    sw1 += __shfl_xor_sync(~0u, sw1, 2);
    float iw0 = (1.f - spv) / sw0, iw1 = (1.f - spv) / sw1;

    int r0 = qt * 128 + w * 16 + g;
    #pragma unroll
    for (int dp = 0; dp < 8; dp++) {
        int col = h * 64 + dp * 8 + 2 * c;
        float2 o0 = make_float2(spv * accA[dp][0] + iw0 * accW[dp][0],
                                spv * accA[dp][1] + iw0 * accW[dp][1]);
        *(float2*)&ob[(n * T_ + r0) * D_ + col] = o0;
        float2 o1 = make_float2(spv * accA[dp][2] + iw1 * accW[dp][2],
                                spv * accA[dp][3] + iw1 * accW[dp][3]);
        *(float2*)&ob[(n * T_ + r0 + 8) * D_ + col] = o1;
    }
}

// ---------------------------------------------------------------------------
extern "C" void kernel_launch(void* const* d_in, const int* in_sizes, int n_in,
                              void* d_out, int out_size) {
    const float* x   = (const float*)d_in[0];
    const float* y   = (const float*)d_in[1];
    const float* iw  = (const float*)d_in[2];
    const float* lw  = (const float*)d_in[3];
    const float* isc = (const float*)d_in[4];
    const float* lsc = (const float*)d_in[5];
    const float* sp  = (const float*)d_in[6];
    float* out = (float*)d_out;

    const int ATTN_SMEM = SMEM_WORDS * 4;   // 67072 bytes
    cudaFuncSetAttribute(attn_kernel, cudaFuncAttributeMaxDynamicSharedMemorySize, ATTN_SMEM);

    scale_kernel<<<1, 32>>>(isc, lsc);

    dim3 g1(1536 / 64, 4096 / 64);
    qkv_kernel<<<g1, 256>>>(x, iw, 0);
    qkv_kernel<<<g1, 256>>>(y, lw, 1);

    dim3 g2(T_ / 128, H_, 4);
    attn_kernel<<<g2, 256, ATTN_SMEM>>>(sp, out);
}

// round 5
// speedup vs baseline: 3.2657x; 1.0240x over previous
#include <cuda_runtime.h>
#include <cstdint>

#define N_  2
#define T_  2048
#define D_  512
#define H_  8
#define HD_ 64
#define NTD (N_*T_*D_)
#define NHTHD (N_*H_*T_*HD_)
#define PAD 68

// Scratch: [stream][q/k/v][n,h,t,hd]
__device__ float g_buf[2][3][NHTHD];
__device__ float g_sc[2][H_*HD_];
// p scratch: [blk(512)][warp(8)][kt(32)][j(8)*lane(32)] float4 (A-frag layout)
__device__ float4 g_p[512u*8u*32u*256u];

// attn smem word offsets
#define QP 0        // pass1 qpack: 64 frag-groups * 132
#define KP 8448     // pass1 kpack: 64 frag-groups * 66
#define MR 12672    // running-max table: 8 warps * 512
#define VC 0        // pass2 vcpack 64 * 66
#define VF 4224     // pass2 vfpack 64 * 66
#define CR 8448     // pass2 corr table 8 * 512
#define SW 12544    // pass2 anti row-sum table (128)
#define SMEM_WORDS 16768

// ---------------------------------------------------------------------------
__global__ void scale_kernel(const float* __restrict__ isc,
                             const float* __restrict__ lsc) {
    int i = threadIdx.x;
    if (i >= 16) return;
    int s = i >> 3, h = i & 7;
    const float* src = (s == 0 ? isc : lsc) + h * HD_;
    float m = -1e30f;
    for (int d = 0; d < HD_; d++) m = fmaxf(m, src[d]);
    float Z = 0.f;
    for (int d = 0; d < HD_; d++) Z += __expf(src[d] - m);
    float inv = 1.f / Z;
    for (int d = 0; d < HD_; d++) g_sc[s][h*HD_ + d] = __expf(src[d] - m) * inv;
}

__device__ __forceinline__ void fma44(float (&acc)[4][4], float4 a, float4 b) {
    acc[0][0] += a.x*b.x; acc[0][1] += a.x*b.y; acc[0][2] += a.x*b.z; acc[0][3] += a.x*b.w;
    acc[1][0] += a.y*b.x; acc[1][1] += a.y*b.y; acc[1][2] += a.y*b.z; acc[1][3] += a.y*b.w;
    acc[2][0] += a.z*b.x; acc[2][1] += a.z*b.y; acc[2][2] += a.z*b.z; acc[2][3] += a.z*b.w;
    acc[3][0] += a.w*b.x; acc[3][1] += a.w*b.y; acc[3][2] += a.w*b.z; acc[3][3] += a.w*b.w;
}

__device__ __forceinline__ uint32_t f2tf(float x) {
    uint32_t r;
    asm("cvt.rna.tf32.f32 %0, %1;" : "=r"(r) : "f"(x));
    return r;
}

__device__ __forceinline__ void mma_tf32(float (&d)[4],
                                         uint32_t a0, uint32_t a1, uint32_t a2, uint32_t a3,
                                         uint32_t b0, uint32_t b1) {
    asm volatile(
        "mma.sync.aligned.m16n8k8.row.col.f32.tf32.tf32.f32 "
        "{%0,%1,%2,%3}, {%4,%5,%6,%7}, {%8,%9}, {%0,%1,%2,%3};"
        : "+f"(d[0]), "+f"(d[1]), "+f"(d[2]), "+f"(d[3])
        : "r"(a0), "r"(a1), "r"(a2), "r"(a3), "r"(b0), "r"(b1));
}

// ---------------------------------------------------------------------------
// Kernel 2a: Q/K projections in tf32 mma. Tile 128(M) x 64(N), K=512.
// 8 warps: warp = 32 rows x 32 cols. Register-prefetched gmem loads.
// cols [0,1024): three = col>>9 (0=q, 1=k)
// ---------------------------------------------------------------------------
__global__ __launch_bounds__(256, 2)
void qk_tf32_kernel(const float* __restrict__ z, const float* __restrict__ W, int stream) {
    __shared__ uint32_t ap[4224];   // A-frags: 8 rowblocks * 4 ks * 132
    __shared__ uint32_t bp[2112];   // B-frags: 8 colblocks * 4 ks * 66
    int tid = threadIdx.x;
    int w = tid >> 5, lane = tid & 31;
    int g = lane >> 2, c = lane & 3;
    int rq = w & 3, nh = w >> 2;
    int c0 = blockIdx.x * 64;
    int m0 = blockIdx.y * 128;

    float acc[2][4][4];
    #pragma unroll
    for (int a = 0; a < 2; a++)
        #pragma unroll
        for (int b = 0; b < 4; b++)
            #pragma unroll
            for (int e = 0; e < 4; e++) acc[a][b][e] = 0.f;

    // prefetch iter 0
    float4 zr[4], wr[2];
    #pragma unroll
    for (int p = 0; p < 4; p++) {
        int i4 = tid + p * 256;
        zr[p] = *(const float4*)&z[(m0 + (i4 >> 3)) * 512 + (i4 & 7) * 4];
    }
    #pragma unroll
    for (int p = 0; p < 2; p++) {
        int i4 = tid + p * 256;
        wr[p] = *(const float4*)&W[(c0 + (i4 >> 3)) * 512 + (i4 & 7) * 4];
    }

    for (int it = 0; it < 16; it++) {
        __syncthreads();
        #pragma unroll
        for (int p = 0; p < 4; p++) {
            int i4 = tid + p * 256;
            int row = i4 >> 3, kq = i4 & 7;
            int base = ((row >> 4) * 4 + (kq >> 1)) * 132 + (row & 7) * 16
                     + (kq & 1) * 2 + ((row >> 3) & 1);
            ap[base + 0]  = f2tf(zr[p].x);
            ap[base + 4]  = f2tf(zr[p].y);
            ap[base + 8]  = f2tf(zr[p].z);
            ap[base + 12] = f2tf(zr[p].w);
        }
        #pragma unroll
        for (int p = 0; p < 2; p++) {
            int i4 = tid + p * 256;
            int col = i4 >> 3, kq = i4 & 7;
            int base = ((col >> 3) * 4 + (kq >> 1)) * 66 + (col & 7) * 8 + (kq & 1);
            bp[base + 0] = f2tf(wr[p].x);
            bp[base + 2] = f2tf(wr[p].y);
            bp[base + 4] = f2tf(wr[p].z);
            bp[base + 6] = f2tf(wr[p].w);
        }
        __syncthreads();
        if (it < 15) {
            int k0 = (it + 1) * 32;
            #pragma unroll
            for (int p = 0; p < 4; p++) {
                int i4 = tid + p * 256;
                zr[p] = *(const float4*)&z[(m0 + (i4 >> 3)) * 512 + k0 + (i4 & 7) * 4];
            }
            #pragma unroll
            for (int p = 0; p < 2; p++) {
                int i4 = tid + p * 256;
                wr[p] = *(const float4*)&W[(c0 + (i4 >> 3)) * 512 + k0 + (i4 & 7) * 4];
            }
        }
        #pragma unroll
        for (int ks = 0; ks < 4; ks++) {
            uint4 a0 = *(const uint4*)&ap[((rq * 2 + 0) * 4 + ks) * 132 + lane * 4];
            uint4 a1 = *(const uint4*)&ap[((rq * 2 + 1) * 4 + ks) * 132 + lane * 4];
            #pragma unroll
            for (int np = 0; np < 4; np++) {
                uint2 b = *(const uint2*)&bp[((nh * 4 + np) * 4 + ks) * 66 + lane * 2];
                mma_tf32(acc[0][np], a0.x, a0.y, a0.z, a0.w, b.x, b.y);
                mma_tf32(acc[1][np], a1.x, a1.y, a1.z, a1.w, b.x, b.y);
            }
        }
    }

    int three = c0 >> 9;
    int h = (c0 >> 6) & 7;
    float* dst = g_buf[stream][three];
    bool isq = (three == 0);
    #pragma unroll
    for (int grp = 0; grp < 2; grp++) {
        #pragma unroll
        for (int np = 0; np < 4; np++) {
            int colb = nh * 32 + np * 8 + 2 * c;
            float2 sc = make_float2(1.f, 1.f);
            if (isq) sc = *(const float2*)&g_sc[stream][h * 64 + colb];
            int m = m0 + rq * 32 + grp * 16 + g;
            int nn = m >> 11, t = m & 2047;
            *(float2*)&dst[((nn * 8 + h) * 2048 + t) * 64 + colb] =
                make_float2(acc[grp][np][0] * sc.x, acc[grp][np][1] * sc.y);
            int m2 = m + 8;
            int nn2 = m2 >> 11, t2 = m2 & 2047;
            *(float2*)&dst[((nn2 * 8 + h) * 2048 + t2) * 64 + colb] =
                make_float2(acc[grp][np][2] * sc.x, acc[grp][np][3] * sc.y);
        }
    }
}

// ---------------------------------------------------------------------------
// Kernel 2b: V projection fp32 FFMA (cols [1024,1536))
// ---------------------------------------------------------------------------
__global__ __launch_bounds__(256, 2)
void v_fp32_kernel(const float* __restrict__ z, const float* __restrict__ W, int stream) {
    __shared__ float as[32][PAD];
    __shared__ float bs[32][PAD];
    int tid = threadIdx.x;
    int ty = tid >> 4, tx = tid & 15;
    int c0 = 1024 + blockIdx.x * 64;
    int m0 = blockIdx.y * 64;

    float acc[4][4] = {};
    for (int k0 = 0; k0 < 512; k0 += 32) {
        __syncthreads();
        #pragma unroll
        for (int p = 0; p < 8; p++) {
            int idx = tid + p * 256;
            int mm = idx >> 5, kk = idx & 31;
            as[kk][mm] = z[(m0 + mm) * 512 + k0 + kk];
            bs[kk][mm] = W[(c0 + mm) * 512 + k0 + kk];
        }
        __syncthreads();
        #pragma unroll
        for (int k = 0; k < 32; k++) {
            float4 av = *(const float4*)&as[k][ty * 4];
            float4 bv = *(const float4*)&bs[k][tx * 4];
            fma44(acc, av, bv);
        }
    }

    int h = (c0 >> 6) & 7;
    float* dst = g_buf[stream][2];
    int hd = tx * 4;
    #pragma unroll
    for (int i = 0; i < 4; i++) {
        int mm = m0 + ty * 4 + i;
        int nn = mm >> 11, t = mm & 2047;
        *(float4*)&dst[((nn * H_ + h) * T_ + t) * HD_ + hd] =
            make_float4(acc[i][0], acc[i][1], acc[i][2], acc[i][3]);
    }
}

// ---------------------------------------------------------------------------
// Kernel 3: dual attention, tf32 mma.sync, two-pass via p-scratch.
// Block = (stream s, batch n, head h, 128-row q-tile). 8 warps.
// Pass 1 (16 rows/warp): QK^T, online (m,Z), p=exp(S-m_run) -> gmem A-frags.
//   K tile register-prefetched.
// Pass 2 (32 rows x 32 dcols/warp): attn = p*corr, anti_w = exp(-attn);
//   B-fragments shared across the two row-groups.
// anti = softmax(max(attn)-attn) == softmax(-attn)
// ---------------------------------------------------------------------------
__global__ __launch_bounds__(256, 2)
void attn_kernel(const float* __restrict__ sp, float* __restrict__ out) {
    extern __shared__ uint32_t smu[];
    float* smf = (float*)smu;
    int tid = threadIdx.x;
    int w = tid >> 5, lane = tid & 31;
    int g = lane >> 2, c = lane & 3;
    int qt = blockIdx.x, h = blockIdx.y, zb = blockIdx.z;
    int s = zb >> 1, n = zb & 1;
    int blk = (zb * 8 + h) * 16 + qt;

    const float* Qb  = g_buf[s][0]     + ((n * H_ + h) * T_ + qt * 128) * HD_;
    const float* Kb  = g_buf[1 - s][1] + ((n * H_ + h) * T_) * HD_;
    const float* Vcb = g_buf[1 - s][2] + ((n * H_ + h) * T_) * HD_;
    const float* Vsb = g_buf[s][2]     + ((n * H_ + h) * T_) * HD_;
    float* ob = out + s * NTD;
    float spv = *sp;

    // pack Q tile [128x64] into tf32 A-fragment layout
    #pragma unroll
    for (int p = 0; p < 8; p++) {
        int i4 = tid + p * 256;
        int row = i4 >> 4, kq = i4 & 15;
        float4 qv = *(const float4*)&Qb[row * 64 + kq * 4];
        int base = QP + ((row >> 4) * 8 + (kq >> 1)) * 132 + (row & 7) * 16
                 + (kq & 1) * 2 + ((row >> 3) & 1);
        smu[base + 0]  = f2tf(qv.x);
        smu[base + 4]  = f2tf(qv.y);
        smu[base + 8]  = f2tf(qv.z);
        smu[base + 12] = f2tf(qv.w);
    }

    float m0 = -1e30f, m1 = -1e30f, Z0 = 0.f, Z1 = 0.f;

    // prefetch K tile 0
    float4 kreg[4];
    #pragma unroll
    for (int p = 0; p < 4; p++) {
        int i4 = tid + p * 256;
        kreg[p] = *(const float4*)&Kb[(i4 >> 4) * 64 + (i4 & 15) * 4];
    }

    // ======================= pass 1: QK^T + stats + p =======================
    for (int kt = 0; kt < 32; kt++) {
        __syncthreads();
        #pragma unroll
        for (int p = 0; p < 4; p++) {
            int i4 = tid + p * 256;
            int nn = i4 >> 4, kq = i4 & 15;
            int base = KP + ((nn >> 3) * 8 + (kq >> 1)) * 66 + (nn & 7) * 8 + (kq & 1);
            smu[base + 0] = f2tf(kreg[p].x);
            smu[base + 2] = f2tf(kreg[p].y);
            smu[base + 4] = f2tf(kreg[p].z);
            smu[base + 6] = f2tf(kreg[p].w);
        }
        __syncthreads();
        if (kt < 31) {
            #pragma unroll
            for (int p = 0; p < 4; p++) {
                int i4 = tid + p * 256;
                kreg[p] = *(const float4*)&Kb[((kt + 1) * 64 + (i4 >> 4)) * 64 + (i4 & 15) * 4];
            }
        }

        float S[8][4];
        #pragma unroll
        for (int j = 0; j < 8; j++) { S[j][0]=0.f; S[j][1]=0.f; S[j][2]=0.f; S[j][3]=0.f; }
        #pragma unroll
        for (int ks = 0; ks < 8; ks++) {
            uint4 a = *(const uint4*)&smu[QP + (w * 8 + ks) * 132 + lane * 4];
            #pragma unroll
            for (int j = 0; j < 8; j++) {
                uint2 b = *(const uint2*)&smu[KP + (j * 8 + ks) * 66 + lane * 2];
                mma_tf32(S[j], a.x, a.y, a.z, a.w, b.x, b.y);
            }
        }
        // online stats: rows g (S[j][0..1]) and g+8 (S[j][2..3]), quad-private
        float t0 = -1e30f, t1 = -1e30f;
        #pragma unroll
        for (int j = 0; j < 8; j++) {
            t0 = fmaxf(t0, fmaxf(S[j][0], S[j][1]));
            t1 = fmaxf(t1, fmaxf(S[j][2], S[j][3]));
        }
        t0 = fmaxf(t0, __shfl_xor_sync(~0u, t0, 1));
        t0 = fmaxf(t0, __shfl_xor_sync(~0u, t0, 2));
        t1 = fmaxf(t1, __shfl_xor_sync(~0u, t1, 1));
        t1 = fmaxf(t1, __shfl_xor_sync(~0u, t1, 2));
        float mn0 = fmaxf(m0, t0), mn1 = fmaxf(m1, t1);

        float P[8][4];
        float ps0 = 0.f, ps1 = 0.f;
        #pragma unroll
        for (int j = 0; j < 8; j++) {
            P[j][0] = __expf(S[j][0] - mn0);
            P[j][1] = __expf(S[j][1] - mn0);
            P[j][2] = __expf(S[j][2] - mn1);
            P[j][3] = __expf(S[j][3] - mn1);
            ps0 += P[j][0] + P[j][1];
            ps1 += P[j][2] + P[j][3];
        }
        ps0 += __shfl_xor_sync(~0u, ps0, 1);
        ps0 += __shfl_xor_sync(~0u, ps0, 2);
        ps1 += __shfl_xor_sync(~0u, ps1, 1);
        ps1 += __shfl_xor_sync(~0u, ps1, 2);
        Z0 = Z0 * __expf(m0 - mn0) + ps0; m0 = mn0;
        Z1 = Z1 * __expf(m1 - mn1) + ps1; m1 = mn1;
        if (c == 0) {
            smf[MR + w * 512 + kt * 16 + g]     = mn0;
            smf[MR + w * 512 + kt * 16 + g + 8] = mn1;
        }
        // shuffle C-frag -> A-frag layout; coalesced store of p
        int src1 = (lane & ~3) | (c >> 1);
        int src2 = src1 + 2;
        bool odd = (lane & 1);
        float4* pg = &g_p[((blk * 8 + w) * 32 + kt) * 256 + lane];
        #pragma unroll
        for (int j = 0; j < 8; j++) {
            float x0 = __shfl_sync(~0u, P[j][0], src1);
            float x1 = __shfl_sync(~0u, P[j][1], src1);
            float y0 = __shfl_sync(~0u, P[j][2], src1);
            float y1 = __shfl_sync(~0u, P[j][3], src1);
            float u0 = __shfl_sync(~0u, P[j][0], src2);
            float u1 = __shfl_sync(~0u, P[j][1], src2);
            float v0 = __shfl_sync(~0u, P[j][2], src2);
            float v1 = __shfl_sync(~0u, P[j][3], src2);
            float4 o;
            o.x = odd ? x1 : x0;
            o.y = odd ? y1 : y0;
            o.z = odd ? u1 : u0;
            o.w = odd ? v1 : v0;
            pg[j * 32] = o;
        }
    }

    // =================== corr table: exp(m_run - m_fin)/Z ===================
    float iZ0 = 1.f / Z0, iZ1 = 1.f / Z1;
    __syncthreads();
    #pragma unroll
    for (int i = 0; i < 16; i++) {
        int idx = lane + i * 32;
        int r = idx & 15;
        int srcl = (r & 7) * 4;
        float mfa = __shfl_sync(~0u, m0, srcl);
        float mfb = __shfl_sync(~0u, m1, srcl);
        float iza = __shfl_sync(~0u, iZ0, srcl);
        float izb = __shfl_sync(~0u, iZ1, srcl);
        float mf = (r < 8) ? mfa : mfb;
        float iz = (r < 8) ? iza : izb;
        float mr = smf[MR + w * 512 + idx];
        smf[CR + w * 512 + idx] = __expf(mr - mf) * iz;
    }

    // ======================= pass 2: attn/anti AV ===========================
    // warp = rows [rq*32, rq*32+32) x dcols [dh*32, dh*32+32)
    int rq = w & 3, dh = w >> 2;
    float accA[2][4][4], accW[2][4][4];
    #pragma unroll
    for (int grp = 0; grp < 2; grp++)
        #pragma unroll
        for (int dp = 0; dp < 4; dp++)
            #pragma unroll
            for (int e = 0; e < 4; e++) { accA[grp][dp][e] = 0.f; accW[grp][dp][e] = 0.f; }
    float sw0[2] = {0.f, 0.f}, sw1[2] = {0.f, 0.f};

    for (int kt = 0; kt < 32; kt++) {
        __syncthreads();
        #pragma unroll
        for (int p = 0; p < 4; p++) {
            int i4 = tid + p * 256;
            int key = i4 >> 4, dq = i4 & 15;
            float4 va = *(const float4*)&Vcb[(kt * 64 + key) * 64 + dq * 4];
            float4 vb = *(const float4*)&Vsb[(kt * 64 + key) * 64 + dq * 4];
            int base = ((dq >> 1) * 8 + (key >> 3)) * 66 + (dq & 1) * 32
                     + (key & 3) * 2 + ((key >> 2) & 1);
            smu[VC + base + 0]  = f2tf(va.x);
            smu[VC + base + 8]  = f2tf(va.y);
            smu[VC + base + 16] = f2tf(va.z);
            smu[VC + base + 24] = f2tf(va.w);
            smu[VF + base + 0]  = f2tf(vb.x);
            smu[VF + base + 8]  = f2tf(vb.y);
            smu[VF + base + 16] = f2tf(vb.z);
            smu[VF + base + 24] = f2tf(vb.w);
        }
        __syncthreads();
        int pw0 = rq * 2, pw1 = rq * 2 + 1;
        float cr00 = smf[CR + pw0 * 512 + kt * 16 + g];
        float cr01 = smf[CR + pw0 * 512 + kt * 16 + g + 8];
        float cr10 = smf[CR + pw1 * 512 + kt * 16 + g];
        float cr11 = smf[CR + pw1 * 512 + kt * 16 + g + 8];
        const float4* pg0 = &g_p[((blk * 8 + pw0) * 32 + kt) * 256 + lane];
        const float4* pg1 = &g_p[((blk * 8 + pw1) * 32 + kt) * 256 + lane];
        #pragma unroll
        for (int j = 0; j < 8; j++) {
            float4 p0 = pg0[j * 32];
            float4 p1 = pg1[j * 32];
            float a00 = p0.x * cr00, a01 = p0.y * cr01, a02 = p0.z * cr00, a03 = p0.w * cr01;
            float a10 = p1.x * cr10, a11 = p1.y * cr11, a12 = p1.z * cr10, a13 = p1.w * cr11;
            float w00 = __expf(-a00), w01 = __expf(-a01), w02 = __expf(-a02), w03 = __expf(-a03);
            float w10 = __expf(-a10), w11 = __expf(-a11), w12 = __expf(-a12), w13 = __expf(-a13);
            sw0[0] += w00 + w02; sw1[0] += w01 + w03;
            sw0[1] += w10 + w12; sw1[1] += w11 + w13;
            uint32_t A00=f2tf(a00), A01=f2tf(a01), A02=f2tf(a02), A03=f2tf(a03);
            uint32_t A10=f2tf(a10), A11=f2tf(a11), A12=f2tf(a12), A13=f2tf(a13);
            uint32_t W00=f2tf(w00), W01=f2tf(w01), W02=f2tf(w02), W03=f2tf(w03);
            uint32_t W10=f2tf(w10), W11=f2tf(w11), W12=f2tf(w12), W13=f2tf(w13);
            #pragma unroll
            for (int dp = 0; dp < 4; dp++) {
                int dg = dh * 4 + dp;
                uint2 bc = *(const uint2*)&smu[VC + (dg * 8 + j) * 66 + lane * 2];
                uint2 bf = *(const uint2*)&smu[VF + (dg * 8 + j) * 66 + lane * 2];
                mma_tf32(accA[0][dp], A00, A01, A02, A03, bc.x, bc.y);
                mma_tf32(accA[1][dp], A10, A11, A12, A13, bc.x, bc.y);
                mma_tf32(accW[0][dp], W00, W01, W02, W03, bf.x, bf.y);
                mma_tf32(accW[1][dp], W10, W11, W12, W13, bf.x, bf.y);
            }
        }
    }

    // anti row sums: quad-reduce, publish from dh==0 warps, broadcast
    #pragma unroll
    for (int grp = 0; grp < 2; grp++) {
        sw0[grp] += __shfl_xor_sync(~0u, sw0[grp], 1);
        sw0[grp] += __shfl_xor_sync(~0u, sw0[grp], 2);
        sw1[grp] += __shfl_xor_sync(~0u, sw1[grp], 1);
        sw1[grp] += __shfl_xor_sync(~0u, sw1[grp], 2);
    }
    __syncthreads();
    if (dh == 0 && c == 0) {
        #pragma unroll
        for (int grp = 0; grp < 2; grp++) {
            smf[SW + rq * 32 + grp * 16 + g]     = sw0[grp];
            smf[SW + rq * 32 + grp * 16 + g + 8] = sw1[grp];
        }
    }
    __syncthreads();

    #pragma unroll
    for (int grp = 0; grp < 2; grp++) {
        int r = rq * 32 + grp * 16 + g;
        float iw0 = (1.f - spv) / smf[SW + r];
        float iw1 = (1.f - spv) / smf[SW + r + 8];
        int t0r = qt * 128 + r;
        #pragma unroll
        for (int dp = 0; dp < 4; dp++) {
            int col = h * 64 + dh * 32 + dp * 8 + 2 * c;
            *(float2*)&ob[(n * T_ + t0r) * D_ + col] =
                make_float2(spv * accA[grp][dp][0] + iw0 * accW[grp][dp][0],
                            spv * accA[grp][dp][1] + iw0 * accW[grp][dp][1]);
            *(float2*)&ob[(n * T_ + t0r + 8) * D_ + col] =
                make_float2(spv * accA[grp][dp][2] + iw1 * accW[grp][dp][2],
                            spv * accA[grp][dp][3] + iw1 * accW[grp][dp][3]);
        }
    }
}

// ---------------------------------------------------------------------------
extern "C" void kernel_launch(void* const* d_in, const int* in_sizes, int n_in,
                              void* d_out, int out_size) {
    const float* x   = (const float*)d_in[0];
    const float* y   = (const float*)d_in[1];
    const float* iw  = (const float*)d_in[2];
    const float* lw  = (const float*)d_in[3];
    const float* isc = (const float*)d_in[4];
    const float* lsc = (const float*)d_in[5];
    const float* sp  = (const float*)d_in[6];
    float* out = (float*)d_out;

    const int ATTN_SMEM = SMEM_WORDS * 4;   // 67072 bytes
    cudaFuncSetAttribute(attn_kernel, cudaFuncAttributeMaxDynamicSharedMemorySize, ATTN_SMEM);

    scale_kernel<<<1, 32>>>(isc, lsc);

    dim3 gqk(1024 / 64, 4096 / 128);
    qk_tf32_kernel<<<gqk, 256>>>(x, iw, 0);
    qk_tf32_kernel<<<gqk, 256>>>(y, lw, 1);
    dim3 gv(512 / 64, 4096 / 64);
    v_fp32_kernel<<<gv, 256>>>(x, iw, 0);
    v_fp32_kernel<<<gv, 256>>>(y, lw, 1);

    dim3 g2(T_ / 128, H_, 4);
    attn_kernel<<<g2, 256, ATTN_SMEM>>>(sp, out);
}